// round 12
// baseline (speedup 1.0000x reference)
#include <cuda_runtime.h>
#include <math.h>
#include <stdint.h>

#define BS 2
#define NF 8
#define NQ 300
#define HH 96
#define WW 96
#define HW (HH*WW)           // 9216
#define DTOT (NF*HW)         // 73728 per batch
#define WPR 3                // 3 uint32 words per 96-col row
#define THR 384              // 12 warps
#define GRID 296             // exactly one wave at 2 blocks/SM
#define HALFG 148
#define TPB 2400             // tiles per batch (NQ*NF)
#define TILE_BYTES (HW*4)    // 36864
#define LN2F 0.6931471805599453f

// ---------------- device scratch (no allocations allowed) ----------------
__device__ unsigned g_tbits[BS*NF*HH*WPR];  // target mask bits per (b,f)
__device__ unsigned g_pbits[BS*HH*WPR];     // pad bits per b
__device__ float g_trm  [BS*NF*WW];         // target max over h, per w  (tgt_y)
__device__ float g_tcm  [BS*NF*HH];         // target max over w, per h  (tgt_x)
__device__ float g_tscal[BS*NF*4];          // {tsum, TTY=sum(trm), TTX=sum(tcm), -}
__device__ float g_rec  [BS*NQ*NF*8];       // {focal, thsum, thp, sx, stx, sy, sty, -}
__device__ unsigned g_count = 0;

struct SmLayout {
    unsigned long long mbar[2];       // 16 B
    float    buf[2][HW];              // 73728 B
    unsigned tb[NF*HH*WPR];           // 9216 B (this block's b only)
    unsigned pb[HH*WPR];              // 1152 B
    float    rowpart[HH*25];          // 9600 B
    float    colpart[16*WW];          // 6144 B
    float    red[12*3];
    float    red2[6][2];
    float    sC[BS*NQ];               // 2400 B (epilogue)
    float    avm[12];
    int      aim[12];
    int      isLast;
};  // ~102.6 KB -> 2 blocks/SM

__device__ __forceinline__ float sigf(float x){
    float e   = __expf(-fabsf(x));
    float inv = __fdividef(1.f, 1.f + e);
    return (x >= 0.f) ? inv : 1.f - inv;
}
__device__ __forceinline__ float tanh_approx(float x){
    float r; asm("tanh.approx.f32 %0, %1;" : "=f"(r) : "f"(x)); return r;
}
__device__ __forceinline__ unsigned smem_u32(const void* p){
    unsigned a;
    asm("{ .reg .u64 t; cvta.to.shared.u64 t, %1; cvt.u32.u64 %0, t; }" : "=r"(a) : "l"(p));
    return a;
}
__device__ __forceinline__ void mbar_init(unsigned mbar, unsigned cnt){
    asm volatile("mbarrier.init.shared.b64 [%0], %1;" :: "r"(mbar), "r"(cnt) : "memory");
}
__device__ __forceinline__ void mbar_expect_tx(unsigned mbar, unsigned bytes){
    asm volatile("mbarrier.arrive.expect_tx.shared.b64 _, [%0], %1;" :: "r"(mbar), "r"(bytes) : "memory");
}
__device__ __forceinline__ void bulk_g2s(unsigned dst, const void* src, unsigned bytes, unsigned mbar){
    asm volatile("cp.async.bulk.shared::cta.global.mbarrier::complete_tx::bytes [%0], [%1], %2, [%3];"
                 :: "r"(dst), "l"(src), "r"(bytes), "r"(mbar) : "memory");
}
__device__ __forceinline__ void mbar_wait(unsigned mbar, unsigned parity){
    asm volatile(
        "{\n\t"
        ".reg .pred P;\n\t"
        "WL_%=:\n\t"
        "mbarrier.try_wait.parity.acquire.cta.shared::cta.b64 P, [%0], %1, 0x989680;\n\t"
        "@P bra.uni WD_%=;\n\t"
        "bra.uni WL_%=;\n\t"
        "WD_%=:\n\t"
        "}"
        :: "r"(mbar), "r"(parity) : "memory");
}

// ---------------- kernel A: target reductions + bit packing ----------------
__global__ __launch_bounds__(256) void tgt_kernel(const float* __restrict__ tmask,
                                                  const unsigned char* __restrict__ pad){
    int b = blockIdx.x / NF, f = blockIdx.x % NF;
    int bf = b*NF + f;
    int tid = threadIdx.x, lane = tid & 31, wid = tid >> 5;

    if (blockIdx.x == 0 && tid == 0) g_count = 0;

    __shared__ float tile[HH*97];
    __shared__ float sred[8][3];

    const float4* tm4 = (const float4*)(tmask + (size_t)bf*HW);
    for (int i = tid; i < HH*24; i += 256){
        int r = i / 24, c = i % 24;
        float4 v = tm4[i];
        tile[r*97 + 4*c+0] = v.x; tile[r*97 + 4*c+1] = v.y;
        tile[r*97 + 4*c+2] = v.z; tile[r*97 + 4*c+3] = v.w;
    }
    __syncthreads();

    for (int rr = 0; rr < 12; rr++){
        int r = wid*12 + rr;
        #pragma unroll
        for (int w3 = 0; w3 < 3; w3++){
            unsigned ball = __ballot_sync(0xffffffffu, tile[r*97 + w3*32 + lane] > 0.5f);
            if (lane == 0) g_tbits[bf*HH*WPR + r*WPR + w3] = ball;
        }
    }
    if (f == 0){
        const unsigned char* pd = pad + (size_t)b*HW;
        for (int rr = 0; rr < 12; rr++){
            int r = wid*12 + rr;
            #pragma unroll
            for (int w3 = 0; w3 < 3; w3++){
                unsigned ball = __ballot_sync(0xffffffffu, pd[r*WW + w3*32 + lane] != 0);
                if (lane == 0) g_pbits[b*HH*WPR + r*WPR + w3] = ball;
            }
        }
    }

    float va = 0.f, vb = 0.f, vc = 0.f;
    if (tid < 96){
        float m = -INFINITY, s = 0.f;
        for (int h = 0; h < HH; h++){
            float v = tile[h*97 + tid];
            m = fmaxf(m, v); s += v;
        }
        g_trm[bf*WW + tid] = m;
        va = s; vb = m;
    } else if (tid < 192){
        int h = tid - 96;
        float m2 = -INFINITY;
        for (int w = 0; w < WW; w++) m2 = fmaxf(m2, tile[h*97 + w]);
        g_tcm[bf*HH + h] = m2;
        vc = m2;
    }
    #pragma unroll
    for (int off = 16; off; off >>= 1){
        va += __shfl_down_sync(0xffffffffu, va, off);
        vb += __shfl_down_sync(0xffffffffu, vb, off);
        vc += __shfl_down_sync(0xffffffffu, vc, off);
    }
    if (lane == 0){ sred[wid][0] = va; sred[wid][1] = vb; sred[wid][2] = vc; }
    __syncthreads();
    if (tid == 0){
        float s0=0, s1=0, s2=0;
        #pragma unroll
        for (int w = 0; w < 8; w++){ s0 += sred[w][0]; s1 += sred[w][1]; s2 += sred[w][2]; }
        g_tscal[bf*4+0] = s0; g_tscal[bf*4+1] = s1; g_tscal[bf*4+2] = s2;
    }
}

// ---------------- epilogue helper: full cost for one (b,q) ----------------
__device__ float cost_pair(int b, int q,
                           const float* __restrict__ logits,
                           const float* __restrict__ boxes,
                           const float* __restrict__ tbox,
                           const int*   __restrict__ tvalid)
{
    float F=0, TH=0, THP=0, SX=0, STX=0, SY=0, STY=0;
    float TS=0, TTY=0, TTX=0, wsum=0, cc=0, bbsum=0, gsum=0;
    #pragma unroll
    for (int f = 0; f < NF; f++){
        int bf = b*NF + f;
        const float* rec = &g_rec[((size_t)(b*NQ + q)*NF + f)*8];
        F   += rec[0]; TH  += rec[1]; THP += rec[2];
        SX  += rec[3]; STX += rec[4]; SY  += rec[5]; STY += rec[6];
        TS  += g_tscal[bf*4+0];
        TTY += g_tscal[bf*4+1];
        TTX += g_tscal[bf*4+2];

        float wf = (tvalid[bf] != 0) ? 1.f : 0.f;
        wsum += wf;
        float lg = logits[bf*NQ + q];
        float pp;
        if (lg >= 0.f){ float e = expf(-lg); pp = 1.f/(1.f+e); }
        else          { float e = expf( lg); pp = e/(1.f+e); }
        float pos = 0.25f*(1.f-pp)*(1.f-pp)*(-logf(pp + 1e-8f));
        float neg = 0.75f*pp*pp*(-logf(1.f - pp + 1e-8f));
        cc += (pos - neg)*wf;

        const float* sb = boxes + (size_t)(bf*NQ + q)*4;
        const float* tb = tbox  + (size_t)bf*4;
        float scx=sb[0], scy=sb[1], sw=sb[2], sh=sb[3];
        float tcx=tb[0], tcy=tb[1], tw=tb[2], th=tb[3];
        bbsum += fabsf(scx-tcx) + fabsf(scy-tcy) + fabsf(sw-tw) + fabsf(sh-th);

        float sx0=scx-0.5f*sw, sy0=scy-0.5f*sh, sx1=scx+0.5f*sw, sy1=scy+0.5f*sh;
        float tx0=tcx-0.5f*tw, ty0=tcy-0.5f*th, tx1=tcx+0.5f*tw, ty1=tcy+0.5f*th;
        float a1=(sx1-sx0)*(sy1-sy0);
        float a2=(tx1-tx0)*(ty1-ty0);
        float ltx=fmaxf(sx0,tx0), lty=fmaxf(sy0,ty0);
        float rbx=fminf(sx1,tx1), rby=fminf(sy1,ty1);
        float iw=fmaxf(rbx-ltx,0.f), ih=fmaxf(rby-lty,0.f);
        float inter=iw*ih;
        float uni=a1+a2-inter;
        float iou=inter/uni;
        float cx0=fminf(sx0,tx0), cy0=fminf(sy0,ty0);
        float cx1=fmaxf(sx1,tx1), cy1=fmaxf(sy1,ty1);
        float cw=fmaxf(cx1-cx0,0.f), ch=fmaxf(cy1-cy0,0.f);
        float ac=cw*ch;
        gsum += iou - (ac-uni)/ac;
    }
    float S  = 0.5f*(float)DTOT + 0.5f*TH;
    float ST = 0.5f*TS + 0.5f*THP;
    float cost_mask = F / (float)DTOT;
    float cost_dice = -(2.f*ST + 1.f) / (S + TS + 1.f);
    float cost_proj = -0.5f * ( (2.f*STX + 1.f)/(SX + TTX + 1.f)
                              + (2.f*STY + 1.f)/(SY + TTY + 1.f) );
    return cc/wsum + bbsum/(float)NF - gsum/(float)NF + cost_mask + cost_dice + cost_proj;
}

// ---------------- kernel B: flat tile schedule, 296 blocks, bulk pipeline ----------------
__global__ __launch_bounds__(THR, 2) void main_kernel(
    const float* __restrict__ masks,
    const float* __restrict__ logits,
    const float* __restrict__ boxes,
    const float* __restrict__ tbox,
    const int*   __restrict__ tvalid,
    float* __restrict__ outf, int out_size)
{
    extern __shared__ char smem_raw[];
    SmLayout* s = (SmLayout*)smem_raw;

    int bx  = blockIdx.x;
    int b   = bx / HALFG;          // 0 or 1
    int r00 = bx % HALFG;          // tile stride start within batch
    int tid = threadIdx.x, lane = tid & 31, wid = tid >> 5;

    unsigned mb0 = smem_u32(&s->mbar[0]);
    unsigned mb1 = smem_u32(&s->mbar[1]);
    unsigned bufaddr0 = smem_u32(&s->buf[0][0]);
    unsigned bufaddr1 = smem_u32(&s->buf[1][0]);

    if (tid == 0){ mbar_init(mb0, 1); mbar_init(mb1, 1); }
    // stage this batch's bit masks
    for (int i = tid; i < NF*HH*WPR; i += THR) s->tb[i] = g_tbits[b*NF*HH*WPR + i];
    for (int i = tid; i < HH*WPR;    i += THR) s->pb[i] = g_pbits[b*HH*WPR + i];
    __syncthreads();

    int nt = (TPB - r00 + HALFG - 1) / HALFG;   // 16 or 17 tiles

    // tile j -> q = j/NF, f = j%NF ; src = masks + ((b*NF+f)*NQ+q)*HW
    if (tid == 0){
        int j0 = r00;
        mbar_expect_tx(mb0, TILE_BYTES);
        bulk_g2s(bufaddr0, masks + ((size_t)((b*NF + (j0%NF))*NQ + j0/NF))*HW, TILE_BYTES, mb0);
        if (nt > 1){
            int j1 = r00 + HALFG;
            mbar_expect_tx(mb1, TILE_BYTES);
            bulk_g2s(bufaddr1, masks + ((size_t)((b*NF + (j1%NF))*NQ + j1/NF))*HW, TILE_BYTES, mb1);
        }
    }

    int fc = tid % 24;          // float4 column
    int r0 = tid / 24;          // 0..15
    int wi = fc >> 3;
    int shb = (4*fc) & 31;

    for (int it = 0; it < nt; it++){
        int j = r00 + it*HALFG;
        int q = j / NF, f = j % NF;
        int cb = it & 1;
        mbar_wait(cb ? mb1 : mb0, (it >> 1) & 1);

        const float4* bb = (const float4*)s->buf[cb];
        const unsigned* tbf = &s->tb[f*HH*WPR];

        float focal = 0.f, thsum = 0.f, thp = 0.f;
        float c0=-INFINITY, c1=-INFINITY, c2=-INFINITY, c3=-INFINITY;
        #pragma unroll
        for (int k = 0; k < 6; k++){
            int r = r0 + 16*k;
            float4 x4 = bb[r*24 + fc];
            unsigned tw = tbf[r*WPR + wi] >> shb;
            unsigned pw = s->pb[r*WPR + wi] >> shb;
            float rmax = -INFINITY;
            float xs[4] = {x4.x, x4.y, x4.z, x4.w};
            #pragma unroll
            for (int jj = 0; jj < 4; jj++){
                float x = ((pw >> jj) & 1u) ? 0.f : xs[jj];
                bool tt = (tw >> jj) & 1u;
                float th = tanh_approx(0.5f * x);
                thsum += th;
                if (tt) thp += th;
                float sgn = tt ? 0.5f : -0.5f;
                float pt  = fmaf(sgn, th, 0.5f);
                float qv  = 1.f - pt;
                float l   = __log2f(fmaxf(pt, 1e-12f));
                float cf  = tt ? (-0.25f*LN2F) : (-0.75f*LN2F);
                focal = fmaf(cf*l, qv*qv, focal);
                rmax = fmaxf(rmax, x);
                if      (jj == 0) c0 = fmaxf(c0, x);
                else if (jj == 1) c1 = fmaxf(c1, x);
                else if (jj == 2) c2 = fmaxf(c2, x);
                else              c3 = fmaxf(c3, x);
            }
            s->rowpart[r*25 + fc] = rmax;
        }
        ((float4*)s->colpart)[r0*24 + fc] = make_float4(c0, c1, c2, c3);
        __syncthreads();   // compute done: buffer free, partials visible

        // refill this buffer with tile it+2
        if (tid == 0 && it + 2 < nt){
            int j2 = r00 + (it+2)*HALFG;
            unsigned mb = cb ? mb1 : mb0;
            mbar_expect_tx(mb, TILE_BYTES);
            bulk_g2s(cb ? bufaddr1 : bufaddr0,
                     masks + ((size_t)((b*NF + (j2%NF))*NQ + j2/NF))*HW, TILE_BYTES, mb);
        }

        // per-tile focal reduction (all 12 warps)
        #pragma unroll
        for (int off = 16; off; off >>= 1){
            focal += __shfl_down_sync(0xffffffffu, focal, off);
            thsum += __shfl_down_sync(0xffffffffu, thsum, off);
            thp   += __shfl_down_sync(0xffffffffu, thp,   off);
        }
        if (lane == 0){ s->red[wid*3] = focal; s->red[wid*3+1] = thsum; s->red[wid*3+2] = thp; }

        // projection tails
        int bf = b*NF + f;
        float a = 0.f, bs = 0.f;
        if (tid < 96){
            int h = tid; float m = -INFINITY;
            #pragma unroll
            for (int c = 0; c < 24; c++) m = fmaxf(m, s->rowpart[h*25 + c]);
            float sp = sigf(m);
            a = sp; bs = sp * __ldg(&g_tcm[bf*HH + h]);
        } else if (tid < 192){
            int w = tid - 96; float m = -INFINITY;
            #pragma unroll
            for (int g = 0; g < 16; g++) m = fmaxf(m, s->colpart[g*WW + w]);
            float sp = sigf(m);
            a = sp; bs = sp * __ldg(&g_trm[bf*WW + w]);
        }
        if (tid < 192){
            #pragma unroll
            for (int off = 16; off; off >>= 1){
                a  += __shfl_down_sync(0xffffffffu, a,  off);
                bs += __shfl_down_sync(0xffffffffu, bs, off);
            }
            if (lane == 0){ s->red2[wid][0] = a; s->red2[wid][1] = bs; }
        }
        __syncthreads();   // red/red2 complete

        if (tid == 0){
            float F=0, TH=0, TP=0;
            #pragma unroll
            for (int w = 0; w < 12; w++){ F += s->red[w*3]; TH += s->red[w*3+1]; TP += s->red[w*3+2]; }
            float sx  = s->red2[0][0]+s->red2[1][0]+s->red2[2][0];
            float stx = s->red2[0][1]+s->red2[1][1]+s->red2[2][1];
            float sy  = s->red2[3][0]+s->red2[4][0]+s->red2[5][0];
            float sty = s->red2[3][1]+s->red2[4][1]+s->red2[5][1];
            float* rec = &g_rec[((size_t)(b*NQ + q)*NF + f)*8];
            rec[0]=F; rec[1]=TH; rec[2]=TP; rec[3]=sx; rec[4]=stx; rec[5]=sy; rec[6]=sty;
        }
        // no extra sync needed: next iteration's red writes occur only after all
        // threads pass the next barrier, which requires tid0 to have finished here
    }

    // ---------------- completion + last-block epilogue ----------------
    if (tid == 0){
        __threadfence();
        unsigned prev = atomicAdd(&g_count, 1u);
        s->isLast = (prev == (unsigned)(GRID - 1));
    }
    __syncthreads();
    if (!s->isLast) return;
    __threadfence();

    for (int i = tid; i < BS*NQ; i += THR){
        int b2 = i / NQ, q2 = i % NQ;
        float c = cost_pair(b2, q2, logits, boxes, tbox, tvalid);
        s->sC[i] = c;
        outf[i] = c;
    }
    __syncthreads();

    for (int b2 = 0; b2 < BS; b2++){
        float v = (tid < NQ) ? s->sC[b2*NQ + tid] : INFINITY;
        int idx = tid;
        #pragma unroll
        for (int off = 16; off; off >>= 1){
            float v2 = __shfl_down_sync(0xffffffffu, v, off);
            int   i2 = __shfl_down_sync(0xffffffffu, idx, off);
            if (v2 < v || (v2 == v && i2 < idx)){ v = v2; idx = i2; }
        }
        if (lane == 0){ s->avm[wid] = v; s->aim[wid] = idx; }
        __syncthreads();
        if (tid == 0){
            float bv = s->avm[0]; int bi = s->aim[0];
            #pragma unroll
            for (int w = 1; w < 12; w++){
                if (s->avm[w] < bv || (s->avm[w] == bv && s->aim[w] < bi)){ bv = s->avm[w]; bi = s->aim[w]; }
            }
            if (out_size == 608){
                long long* ip = (long long*)(outf + BS*NQ);
                ip[b2]      = (long long)bi;
                ip[BS + b2] = 0LL;
            } else if (out_size >= BS*NQ + 2*BS){
                outf[BS*NQ + b2]      = (float)bi;
                outf[BS*NQ + BS + b2] = 0.f;
            }
        }
        __syncthreads();
    }
    if (tid == 0) g_count = 0;   // reset for next graph replay
}

// ---------------- launch ----------------
extern "C" void kernel_launch(void* const* d_in, const int* in_sizes, int n_in,
                              void* d_out, int out_size)
{
    const float* logits = (const float*)d_in[0];
    const float* boxes  = (const float*)d_in[1];
    const float* masks  = (const float*)d_in[2];
    const float* tmask  = (const float*)d_in[3];
    const float* tbox   = (const float*)d_in[4];
    const int*   tvalid = (const int*)d_in[5];
    const unsigned char* pad = (const unsigned char*)d_in[6];
    float* outf = (float*)d_out;

    cudaFuncSetAttribute(main_kernel, cudaFuncAttributeMaxDynamicSharedMemorySize,
                         (int)sizeof(SmLayout));

    tgt_kernel <<<BS*NF, 256>>>(tmask, pad);
    main_kernel<<<GRID,  THR, sizeof(SmLayout)>>>(masks, logits, boxes, tbox, tvalid, outf, out_size);
}

// round 16
// speedup vs baseline: 1.0048x; 1.0048x over previous
#include <cuda_runtime.h>
#include <math.h>
#include <stdint.h>

#define BS 2
#define NF 8
#define NQ 300
#define HH 96
#define WW 96
#define HW (HH*WW)           // 9216
#define DTOT (NF*HW)         // 73728 per batch
#define WPR 3                // 3 uint32 words per 96-col row
#define THR 384              // 12 warps
#define HALFG 148
#define GRID (2*HALFG)       // 296: one wave at 2 blocks/SM
#define TPB 2400             // tiles per batch (NF*NQ)
#define TILE_BYTES (HW*4)    // 36864
#define LN2F 0.6931471805599453f

// ---------------- device scratch (no allocations allowed) ----------------
__device__ unsigned g_tbits[BS*NF*HH*WPR];  // target mask bits per (b,f)
__device__ unsigned g_pbits[BS*HH*WPR];     // pad bits per b
__device__ float g_trm  [BS*NF*WW];         // target max over h, per w  (tgt_y)
__device__ float g_tcm  [BS*NF*HH];         // target max over w, per h  (tgt_x)
__device__ float g_tscal[BS*NF*4];          // {tsum, TTY=sum(trm), TTX=sum(tcm), -}
__device__ float g_rec  [BS*NQ*NF*8];       // {focal, thsum, thp, sx, stx, sy, sty, -}
__device__ unsigned g_count = 0;

struct SmLayout {
    unsigned long long mbar[2];       // 16 B
    float    buf[2][HW];              // 73728 B
    unsigned tb[NF*HH*WPR];           // 9216 B (this block's b only)
    unsigned pb[HH*WPR];              // 1152 B
    float    rowpart[HH*25];          // 9600 B (aliased as sC in epilogue)
    float    colpart[16*WW];          // 6144 B
    float    red[12*3];
    float    red2[6][2];
    float    avm[12];
    int      aim[12];
    int      isLast;
};  // ~100.3 KB -> 2 blocks/SM

__device__ __forceinline__ float sigf(float x){
    float e   = __expf(-fabsf(x));
    float inv = __fdividef(1.f, 1.f + e);
    return (x >= 0.f) ? inv : 1.f - inv;
}
__device__ __forceinline__ float tanh_approx(float x){
    float r; asm("tanh.approx.f32 %0, %1;" : "=f"(r) : "f"(x)); return r;
}
__device__ __forceinline__ unsigned smem_u32(const void* p){
    unsigned a;
    asm("{ .reg .u64 t; cvta.to.shared.u64 t, %1; cvt.u32.u64 %0, t; }" : "=r"(a) : "l"(p));
    return a;
}
__device__ __forceinline__ void mbar_init(unsigned mbar, unsigned cnt){
    asm volatile("mbarrier.init.shared.b64 [%0], %1;" :: "r"(mbar), "r"(cnt) : "memory");
}
__device__ __forceinline__ void mbar_expect_tx(unsigned mbar, unsigned bytes){
    asm volatile("mbarrier.arrive.expect_tx.shared.b64 _, [%0], %1;" :: "r"(mbar), "r"(bytes) : "memory");
}
__device__ __forceinline__ void bulk_g2s(unsigned dst, const void* src, unsigned bytes, unsigned mbar){
    asm volatile("cp.async.bulk.shared::cta.global.mbarrier::complete_tx::bytes [%0], [%1], %2, [%3];"
                 :: "r"(dst), "l"(src), "r"(bytes), "r"(mbar) : "memory");
}
__device__ __forceinline__ void mbar_wait(unsigned mbar, unsigned parity){
    asm volatile(
        "{\n\t"
        ".reg .pred P;\n\t"
        "WL_%=:\n\t"
        "mbarrier.try_wait.parity.acquire.cta.shared::cta.b64 P, [%0], %1, 0x989680;\n\t"
        "@P bra.uni WD_%=;\n\t"
        "bra.uni WL_%=;\n\t"
        "WD_%=:\n\t"
        "}"
        :: "r"(mbar), "r"(parity) : "memory");
}

// ---------------- kernel A: target reductions + bit packing ----------------
__global__ __launch_bounds__(256) void tgt_kernel(const float* __restrict__ tmask,
                                                  const unsigned char* __restrict__ pad){
    int b = blockIdx.x / NF, f = blockIdx.x % NF;
    int bf = b*NF + f;
    int tid = threadIdx.x, lane = tid & 31, wid = tid >> 5;

    if (blockIdx.x == 0 && tid == 0) g_count = 0;

    __shared__ float tile[HH*97];
    __shared__ float sred[8][3];

    const float4* tm4 = (const float4*)(tmask + (size_t)bf*HW);
    for (int i = tid; i < HH*24; i += 256){
        int r = i / 24, c = i % 24;
        float4 v = tm4[i];
        tile[r*97 + 4*c+0] = v.x; tile[r*97 + 4*c+1] = v.y;
        tile[r*97 + 4*c+2] = v.z; tile[r*97 + 4*c+3] = v.w;
    }
    __syncthreads();

    for (int rr = 0; rr < 12; rr++){
        int r = wid*12 + rr;
        #pragma unroll
        for (int w3 = 0; w3 < 3; w3++){
            unsigned ball = __ballot_sync(0xffffffffu, tile[r*97 + w3*32 + lane] > 0.5f);
            if (lane == 0) g_tbits[bf*HH*WPR + r*WPR + w3] = ball;
        }
    }
    if (f == 0){
        const unsigned char* pd = pad + (size_t)b*HW;
        for (int rr = 0; rr < 12; rr++){
            int r = wid*12 + rr;
            #pragma unroll
            for (int w3 = 0; w3 < 3; w3++){
                unsigned ball = __ballot_sync(0xffffffffu, pd[r*WW + w3*32 + lane] != 0);
                if (lane == 0) g_pbits[b*HH*WPR + r*WPR + w3] = ball;
            }
        }
    }

    float va = 0.f, vb = 0.f, vc = 0.f;
    if (tid < 96){
        float m = -INFINITY, s = 0.f;
        for (int h = 0; h < HH; h++){
            float v = tile[h*97 + tid];
            m = fmaxf(m, v); s += v;
        }
        g_trm[bf*WW + tid] = m;
        va = s; vb = m;
    } else if (tid < 192){
        int h = tid - 96;
        float m2 = -INFINITY;
        for (int w = 0; w < WW; w++) m2 = fmaxf(m2, tile[h*97 + w]);
        g_tcm[bf*HH + h] = m2;
        vc = m2;
    }
    #pragma unroll
    for (int off = 16; off; off >>= 1){
        va += __shfl_down_sync(0xffffffffu, va, off);
        vb += __shfl_down_sync(0xffffffffu, vb, off);
        vc += __shfl_down_sync(0xffffffffu, vc, off);
    }
    if (lane == 0){ sred[wid][0] = va; sred[wid][1] = vb; sred[wid][2] = vc; }
    __syncthreads();
    if (tid == 0){
        float s0=0, s1=0, s2=0;
        #pragma unroll
        for (int w = 0; w < 8; w++){ s0 += sred[w][0]; s1 += sred[w][1]; s2 += sred[w][2]; }
        g_tscal[bf*4+0] = s0; g_tscal[bf*4+1] = s1; g_tscal[bf*4+2] = s2;
    }
}

// ---------------- epilogue helper: full cost for one (b,q) ----------------
__device__ float cost_pair(int b, int q,
                           const float* __restrict__ logits,
                           const float* __restrict__ boxes,
                           const float* __restrict__ tbox,
                           const int*   __restrict__ tvalid)
{
    float F=0, TH=0, THP=0, SX=0, STX=0, SY=0, STY=0;
    float TS=0, TTY=0, TTX=0, wsum=0, cc=0, bbsum=0, gsum=0;
    #pragma unroll
    for (int f = 0; f < NF; f++){
        int bf = b*NF + f;
        const float* rec = &g_rec[((size_t)(b*NQ + q)*NF + f)*8];
        F   += rec[0]; TH  += rec[1]; THP += rec[2];
        SX  += rec[3]; STX += rec[4]; SY  += rec[5]; STY += rec[6];
        TS  += g_tscal[bf*4+0];
        TTY += g_tscal[bf*4+1];
        TTX += g_tscal[bf*4+2];

        float wf = (tvalid[bf] != 0) ? 1.f : 0.f;
        wsum += wf;
        float lg = logits[bf*NQ + q];
        float pp;
        if (lg >= 0.f){ float e = expf(-lg); pp = 1.f/(1.f+e); }
        else          { float e = expf( lg); pp = e/(1.f+e); }
        float pos = 0.25f*(1.f-pp)*(1.f-pp)*(-logf(pp + 1e-8f));
        float neg = 0.75f*pp*pp*(-logf(1.f - pp + 1e-8f));
        cc += (pos - neg)*wf;

        const float* sb = boxes + (size_t)(bf*NQ + q)*4;
        const float* tb = tbox  + (size_t)bf*4;
        float scx=sb[0], scy=sb[1], sw=sb[2], sh=sb[3];
        float tcx=tb[0], tcy=tb[1], tw=tb[2], th=tb[3];
        bbsum += fabsf(scx-tcx) + fabsf(scy-tcy) + fabsf(sw-tw) + fabsf(sh-th);

        float sx0=scx-0.5f*sw, sy0=scy-0.5f*sh, sx1=scx+0.5f*sw, sy1=scy+0.5f*sh;
        float tx0=tcx-0.5f*tw, ty0=tcy-0.5f*th, tx1=tcx+0.5f*tw, ty1=tcy+0.5f*th;
        float a1=(sx1-sx0)*(sy1-sy0);
        float a2=(tx1-tx0)*(ty1-ty0);
        float ltx=fmaxf(sx0,tx0), lty=fmaxf(sy0,ty0);
        float rbx=fminf(sx1,tx1), rby=fminf(sy1,ty1);
        float iw=fmaxf(rbx-ltx,0.f), ih=fmaxf(rby-lty,0.f);
        float inter=iw*ih;
        float uni=a1+a2-inter;
        float iou=inter/uni;
        float cx0=fminf(sx0,tx0), cy0=fminf(sy0,ty0);
        float cx1=fmaxf(sx1,tx1), cy1=fmaxf(sy1,ty1);
        float cw=fmaxf(cx1-cx0,0.f), ch=fmaxf(cy1-cy0,0.f);
        float ac=cw*ch;
        gsum += iou - (ac-uni)/ac;
    }
    float S  = 0.5f*(float)DTOT + 0.5f*TH;
    float ST = 0.5f*TS + 0.5f*THP;
    float cost_mask = F / (float)DTOT;
    float cost_dice = -(2.f*ST + 1.f) / (S + TS + 1.f);
    float cost_proj = -0.5f * ( (2.f*STX + 1.f)/(SX + TTX + 1.f)
                              + (2.f*STY + 1.f)/(SY + TTY + 1.f) );
    return cc/wsum + bbsum/(float)NF - gsum/(float)NF + cost_mask + cost_dice + cost_proj;
}

// ---------------- kernel B: contiguous tile chunks, one wave, bulk pipeline ----------------
__global__ __launch_bounds__(THR, 2) void main_kernel(
    const float* __restrict__ masks,
    const float* __restrict__ logits,
    const float* __restrict__ boxes,
    const float* __restrict__ tbox,
    const int*   __restrict__ tvalid,
    float* __restrict__ outf, int out_size)
{
    extern __shared__ char smem_raw[];
    SmLayout* s = (SmLayout*)smem_raw;

    int bx  = blockIdx.x;
    int b   = bx / HALFG;               // 0 or 1
    int rk  = bx % HALFG;               // chunk index within batch
    int tlo = (rk    * TPB) / HALFG;    // contiguous tile range [tlo, thi)
    int thi = ((rk+1)* TPB) / HALFG;    // 16 or 17 tiles, memory-order (f-major, q fast)
    int nt  = thi - tlo;
    int tid = threadIdx.x, lane = tid & 31, wid = tid >> 5;

    unsigned mb0 = smem_u32(&s->mbar[0]);
    unsigned mb1 = smem_u32(&s->mbar[1]);
    unsigned bufaddr0 = smem_u32(&s->buf[0][0]);
    unsigned bufaddr1 = smem_u32(&s->buf[1][0]);

    if (tid == 0){ mbar_init(mb0, 1); mbar_init(mb1, 1); }
    // stage this batch's bit masks
    for (int i = tid; i < NF*HH*WPR; i += THR) s->tb[i] = g_tbits[b*NF*HH*WPR + i];
    for (int i = tid; i < HH*WPR;    i += THR) s->pb[i] = g_pbits[b*HH*WPR + i];
    __syncthreads();

    const float* base = masks + (size_t)(b*TPB + tlo)*HW;   // contiguous stream

    if (tid == 0){
        mbar_expect_tx(mb0, TILE_BYTES);
        bulk_g2s(bufaddr0, base, TILE_BYTES, mb0);
        if (nt > 1){
            mbar_expect_tx(mb1, TILE_BYTES);
            bulk_g2s(bufaddr1, base + HW, TILE_BYTES, mb1);
        }
    }

    int fc = tid % 24;          // float4 column
    int r0 = tid / 24;          // 0..15
    int wi = fc >> 3;
    int shb = (4*fc) & 31;

    for (int it = 0; it < nt; it++){
        int t = tlo + it;               // tile within batch: f = t/NQ, q = t%NQ
        int f = t / NQ;
        int cb = it & 1;
        mbar_wait(cb ? mb1 : mb0, (it >> 1) & 1);

        const float4* bb = (const float4*)s->buf[cb];
        const unsigned* tbf = &s->tb[f*HH*WPR];

        float focal = 0.f, thsum = 0.f, thp = 0.f;
        float c0=-INFINITY, c1=-INFINITY, c2=-INFINITY, c3=-INFINITY;
        #pragma unroll
        for (int k = 0; k < 6; k++){
            int r = r0 + 16*k;
            float4 x4 = bb[r*24 + fc];
            unsigned tw = tbf[r*WPR + wi] >> shb;
            unsigned pw = s->pb[r*WPR + wi] >> shb;
            float rmax = -INFINITY;
            float xs[4] = {x4.x, x4.y, x4.z, x4.w};
            #pragma unroll
            for (int jj = 0; jj < 4; jj++){
                float x = ((pw >> jj) & 1u) ? 0.f : xs[jj];
                bool tt = (tw >> jj) & 1u;
                float th = tanh_approx(0.5f * x);
                thsum += th;
                if (tt) thp += th;
                float sgn = tt ? 0.5f : -0.5f;
                float pt  = fmaf(sgn, th, 0.5f);
                float qv  = 1.f - pt;
                float l   = __log2f(fmaxf(pt, 1e-12f));
                float cf  = tt ? (-0.25f*LN2F) : (-0.75f*LN2F);
                focal = fmaf(cf*l, qv*qv, focal);
                rmax = fmaxf(rmax, x);
                if      (jj == 0) c0 = fmaxf(c0, x);
                else if (jj == 1) c1 = fmaxf(c1, x);
                else if (jj == 2) c2 = fmaxf(c2, x);
                else              c3 = fmaxf(c3, x);
            }
            s->rowpart[r*25 + fc] = rmax;
        }
        ((float4*)s->colpart)[r0*24 + fc] = make_float4(c0, c1, c2, c3);
        __syncthreads();   // compute done: buffer free, partials visible

        // refill this buffer with tile it+2 (next in the contiguous stream)
        if (tid == 0 && it + 2 < nt){
            unsigned mb = cb ? mb1 : mb0;
            mbar_expect_tx(mb, TILE_BYTES);
            bulk_g2s(cb ? bufaddr1 : bufaddr0, base + (size_t)(it+2)*HW, TILE_BYTES, mb);
        }

        // per-tile focal reduction (all 12 warps)
        #pragma unroll
        for (int off = 16; off; off >>= 1){
            focal += __shfl_down_sync(0xffffffffu, focal, off);
            thsum += __shfl_down_sync(0xffffffffu, thsum, off);
            thp   += __shfl_down_sync(0xffffffffu, thp,   off);
        }
        if (lane == 0){ s->red[wid*3] = focal; s->red[wid*3+1] = thsum; s->red[wid*3+2] = thp; }

        // projection tails
        int bf = b*NF + f;
        float a = 0.f, bs = 0.f;
        if (tid < 96){
            int h = tid; float m = -INFINITY;
            #pragma unroll
            for (int c = 0; c < 24; c++) m = fmaxf(m, s->rowpart[h*25 + c]);
            float sp = sigf(m);
            a = sp; bs = sp * __ldg(&g_tcm[bf*HH + h]);
        } else if (tid < 192){
            int w = tid - 96; float m = -INFINITY;
            #pragma unroll
            for (int g = 0; g < 16; g++) m = fmaxf(m, s->colpart[g*WW + w]);
            float sp = sigf(m);
            a = sp; bs = sp * __ldg(&g_trm[bf*WW + w]);
        }
        if (tid < 192){
            #pragma unroll
            for (int off = 16; off; off >>= 1){
                a  += __shfl_down_sync(0xffffffffu, a,  off);
                bs += __shfl_down_sync(0xffffffffu, bs, off);
            }
            if (lane == 0){ s->red2[wid][0] = a; s->red2[wid][1] = bs; }
        }
        __syncthreads();   // red/red2 complete

        if (tid == 0){
            float F=0, TH=0, TP=0;
            #pragma unroll
            for (int w = 0; w < 12; w++){ F += s->red[w*3]; TH += s->red[w*3+1]; TP += s->red[w*3+2]; }
            float sx  = s->red2[0][0]+s->red2[1][0]+s->red2[2][0];
            float stx = s->red2[0][1]+s->red2[1][1]+s->red2[2][1];
            float sy  = s->red2[3][0]+s->red2[4][0]+s->red2[5][0];
            float sty = s->red2[3][1]+s->red2[4][1]+s->red2[5][1];
            int q = t % NQ;
            float* rec = &g_rec[((size_t)(b*NQ + q)*NF + f)*8];
            rec[0]=F; rec[1]=TH; rec[2]=TP; rec[3]=sx; rec[4]=stx; rec[5]=sy; rec[6]=sty;
        }
        // next-iter red writes are gated by this iteration's last barrier + next compute sync
    }

    // ---------------- completion + last-block epilogue ----------------
    if (tid == 0){
        __threadfence();
        unsigned prev = atomicAdd(&g_count, 1u);
        s->isLast = (prev == (unsigned)(GRID - 1));
    }
    __syncthreads();
    if (!s->isLast) return;
    __threadfence();

    float* sC = s->rowpart;   // alias: rowpart no longer needed
    for (int i = tid; i < BS*NQ; i += THR){
        int b2 = i / NQ, q2 = i % NQ;
        float c = cost_pair(b2, q2, logits, boxes, tbox, tvalid);
        sC[i] = c;
        outf[i] = c;
    }
    __syncthreads();

    for (int b2 = 0; b2 < BS; b2++){
        float v = (tid < NQ) ? sC[b2*NQ + tid] : INFINITY;
        int idx = tid;
        #pragma unroll
        for (int off = 16; off; off >>= 1){
            float v2 = __shfl_down_sync(0xffffffffu, v, off);
            int   i2 = __shfl_down_sync(0xffffffffu, idx, off);
            if (v2 < v || (v2 == v && i2 < idx)){ v = v2; idx = i2; }
        }
        if (lane == 0){ s->avm[wid] = v; s->aim[wid] = idx; }
        __syncthreads();
        if (tid == 0){
            float bv = s->avm[0]; int bi = s->aim[0];
            #pragma unroll
            for (int w = 1; w < 12; w++){
                if (s->avm[w] < bv || (s->avm[w] == bv && s->aim[w] < bi)){ bv = s->avm[w]; bi = s->aim[w]; }
            }
            if (out_size == 608){
                long long* ip = (long long*)(outf + BS*NQ);
                ip[b2]      = (long long)bi;
                ip[BS + b2] = 0LL;
            } else if (out_size >= BS*NQ + 2*BS){
                outf[BS*NQ + b2]      = (float)bi;
                outf[BS*NQ + BS + b2] = 0.f;
            }
        }
        __syncthreads();
    }
    if (tid == 0) g_count = 0;   // reset for next graph replay
}

// ---------------- launch ----------------
extern "C" void kernel_launch(void* const* d_in, const int* in_sizes, int n_in,
                              void* d_out, int out_size)
{
    const float* logits = (const float*)d_in[0];
    const float* boxes  = (const float*)d_in[1];
    const float* masks  = (const float*)d_in[2];
    const float* tmask  = (const float*)d_in[3];
    const float* tbox   = (const float*)d_in[4];
    const int*   tvalid = (const int*)d_in[5];
    const unsigned char* pad = (const unsigned char*)d_in[6];
    float* outf = (float*)d_out;

    cudaFuncSetAttribute(main_kernel, cudaFuncAttributeMaxDynamicSharedMemorySize,
                         (int)sizeof(SmLayout));

    tgt_kernel <<<BS*NF, 256>>>(tmask, pad);
    main_kernel<<<GRID,  THR, sizeof(SmLayout)>>>(masks, logits, boxes, tbox, tvalid, outf, out_size);
}

// round 17
// speedup vs baseline: 1.3926x; 1.3859x over previous
#include <cuda_runtime.h>
#include <math.h>
#include <stdint.h>

#define BS 2
#define NF 8
#define NQ 300
#define HH 96
#define WW 96
#define HW (HH*WW)           // 9216
#define DTOT (NF*HW)         // 73728 per batch
#define WPR 3                // 3 uint32 words per 96-col row
#define THR 384              // 12 warps
#define NBQ (BS*NQ)          // 600 blocks
#define HROWS 48             // half-tile rows
#define HELEM (HROWS*WW)     // 4608 floats
#define HBYTES (HELEM*4)     // 18432
#define NSTEP (2*NF)         // 16 half-tile steps
#define LN2F 0.6931471805599453f

// ---------------- device scratch (no allocations allowed) ----------------
__device__ unsigned g_tbits[BS*NF*HH*WPR];  // target mask bits per (b,f)
__device__ unsigned g_pbits[BS*HH*WPR];     // pad bits per b
__device__ float g_trm  [BS*NF*WW];         // target max over h, per w  (tgt_y)
__device__ float g_tcm  [BS*NF*HH];         // target max over w, per h  (tgt_x)
__device__ float g_tscal[BS*NF*4];          // {tsum, TTY=sum(trm), TTX=sum(tcm), -}
__device__ unsigned g_count = 0;

struct SmLayout {
    unsigned long long mbar[4];       // 32 B
    float    buf[4][HELEM];           // 73728 B (depth-4 half-tile ring)
    unsigned tb[NF*HH*WPR];           // 9216 B
    unsigned pb[HH*WPR];              // 1152 B
    float    rowpart[HH*25];          // 9600 B
    float    colpart[16*WW];          // 6144 B
    float    red[12*3];
    float    red2[6][2];
    float    acc[4];                  // SX, STX, SY, STY over f
    float    avm[12];
    int      aim[12];
    int      isLast;
};  // ~100.4 KB -> 2 blocks/SM

__device__ __forceinline__ float sigf(float x){
    float e   = __expf(-fabsf(x));
    float inv = __fdividef(1.f, 1.f + e);
    return (x >= 0.f) ? inv : 1.f - inv;
}
__device__ __forceinline__ float tanh_approx(float x){
    float r; asm("tanh.approx.f32 %0, %1;" : "=f"(r) : "f"(x)); return r;
}
__device__ __forceinline__ unsigned smem_u32(const void* p){
    unsigned a;
    asm("{ .reg .u64 t; cvta.to.shared.u64 t, %1; cvt.u32.u64 %0, t; }" : "=r"(a) : "l"(p));
    return a;
}
__device__ __forceinline__ void mbar_init(unsigned mbar, unsigned cnt){
    asm volatile("mbarrier.init.shared.b64 [%0], %1;" :: "r"(mbar), "r"(cnt) : "memory");
}
__device__ __forceinline__ void mbar_expect_tx(unsigned mbar, unsigned bytes){
    asm volatile("mbarrier.arrive.expect_tx.shared.b64 _, [%0], %1;" :: "r"(mbar), "r"(bytes) : "memory");
}
__device__ __forceinline__ void bulk_g2s(unsigned dst, const void* src, unsigned bytes, unsigned mbar){
    asm volatile("cp.async.bulk.shared::cta.global.mbarrier::complete_tx::bytes [%0], [%1], %2, [%3];"
                 :: "r"(dst), "l"(src), "r"(bytes), "r"(mbar) : "memory");
}
__device__ __forceinline__ void mbar_wait(unsigned mbar, unsigned parity){
    asm volatile(
        "{\n\t"
        ".reg .pred P;\n\t"
        "WL_%=:\n\t"
        "mbarrier.try_wait.parity.acquire.cta.shared::cta.b64 P, [%0], %1, 0x989680;\n\t"
        "@P bra.uni WD_%=;\n\t"
        "bra.uni WL_%=;\n\t"
        "WD_%=:\n\t"
        "}"
        :: "r"(mbar), "r"(parity) : "memory");
}

// ---------------- kernel A: target reductions + bit packing ----------------
__global__ __launch_bounds__(256) void tgt_kernel(const float* __restrict__ tmask,
                                                  const unsigned char* __restrict__ pad){
    int b = blockIdx.x / NF, f = blockIdx.x % NF;
    int bf = b*NF + f;
    int tid = threadIdx.x, lane = tid & 31, wid = tid >> 5;

    if (blockIdx.x == 0 && tid == 0) g_count = 0;

    __shared__ float tile[HH*97];
    __shared__ float sred[8][3];

    const float4* tm4 = (const float4*)(tmask + (size_t)bf*HW);
    for (int i = tid; i < HH*24; i += 256){
        int r = i / 24, c = i % 24;
        float4 v = tm4[i];
        tile[r*97 + 4*c+0] = v.x; tile[r*97 + 4*c+1] = v.y;
        tile[r*97 + 4*c+2] = v.z; tile[r*97 + 4*c+3] = v.w;
    }
    __syncthreads();

    for (int rr = 0; rr < 12; rr++){
        int r = wid*12 + rr;
        #pragma unroll
        for (int w3 = 0; w3 < 3; w3++){
            unsigned ball = __ballot_sync(0xffffffffu, tile[r*97 + w3*32 + lane] > 0.5f);
            if (lane == 0) g_tbits[bf*HH*WPR + r*WPR + w3] = ball;
        }
    }
    if (f == 0){
        const unsigned char* pd = pad + (size_t)b*HW;
        for (int rr = 0; rr < 12; rr++){
            int r = wid*12 + rr;
            #pragma unroll
            for (int w3 = 0; w3 < 3; w3++){
                unsigned ball = __ballot_sync(0xffffffffu, pd[r*WW + w3*32 + lane] != 0);
                if (lane == 0) g_pbits[b*HH*WPR + r*WPR + w3] = ball;
            }
        }
    }

    float va = 0.f, vb = 0.f, vc = 0.f;
    if (tid < 96){
        float m = -INFINITY, s = 0.f;
        for (int h = 0; h < HH; h++){
            float v = tile[h*97 + tid];
            m = fmaxf(m, v); s += v;
        }
        g_trm[bf*WW + tid] = m;
        va = s; vb = m;
    } else if (tid < 192){
        int h = tid - 96;
        float m2 = -INFINITY;
        for (int w = 0; w < WW; w++) m2 = fmaxf(m2, tile[h*97 + w]);
        g_tcm[bf*HH + h] = m2;
        vc = m2;
    }
    #pragma unroll
    for (int off = 16; off; off >>= 1){
        va += __shfl_down_sync(0xffffffffu, va, off);
        vb += __shfl_down_sync(0xffffffffu, vb, off);
        vc += __shfl_down_sync(0xffffffffu, vc, off);
    }
    if (lane == 0){ sred[wid][0] = va; sred[wid][1] = vb; sred[wid][2] = vc; }
    __syncthreads();
    if (tid == 0){
        float s0=0, s1=0, s2=0;
        #pragma unroll
        for (int w = 0; w < 8; w++){ s0 += sred[w][0]; s1 += sred[w][1]; s2 += sred[w][2]; }
        g_tscal[bf*4+0] = s0; g_tscal[bf*4+1] = s1; g_tscal[bf*4+2] = s2;
    }
}

// ---------------- kernel B: one block per (b,q), depth-4 half-tile ring ----------------
__global__ __launch_bounds__(THR, 2) void main_kernel(
    const float* __restrict__ masks,
    const float* __restrict__ logits,
    const float* __restrict__ boxes,
    const float* __restrict__ tbox,
    const int*   __restrict__ tvalid,
    float* __restrict__ outf, int out_size)
{
    extern __shared__ char smem_raw[];
    SmLayout* s = (SmLayout*)smem_raw;

    int b = blockIdx.x / NQ;
    int q = blockIdx.x % NQ;
    int tid = threadIdx.x, lane = tid & 31, wid = tid >> 5;

    unsigned mb[4], ba[4];
    #pragma unroll
    for (int i = 0; i < 4; i++){
        mb[i] = smem_u32(&s->mbar[i]);
        ba[i] = smem_u32(&s->buf[i][0]);
    }

    const float* base0 = masks + ((size_t)((b*NF+0)*NQ + q))*HW;
    const size_t fstride = (size_t)NQ*HW;

    if (tid == 0){
        #pragma unroll
        for (int i = 0; i < 4; i++) mbar_init(mb[i], 1);
        // issue first 4 half-tile loads immediately (f0h0, f0h1, f1h0, f1h1)
        #pragma unroll
        for (int i = 0; i < 4; i++){
            int f0 = i >> 1, h0 = i & 1;
            mbar_expect_tx(mb[i], HBYTES);
            bulk_g2s(ba[i], base0 + (size_t)f0*fstride + h0*HELEM, HBYTES, mb[i]);
        }
        s->acc[0] = s->acc[1] = s->acc[2] = s->acc[3] = 0.f;
    }
    // stage bit masks (overlaps with in-flight TMA)
    for (int i = tid; i < NF*HH*WPR; i += THR) s->tb[i] = g_tbits[b*NF*HH*WPR + i];
    for (int i = tid; i < HH*WPR;    i += THR) s->pb[i] = g_pbits[b*HH*WPR + i];
    __syncthreads();

    int fc = tid % 24;          // float4 column
    int r0 = tid / 24;          // 0..15
    int wi = fc >> 3;
    int shb = (4*fc) & 31;

    float focal = 0.f, thsum = 0.f, thp = 0.f;

    #pragma unroll
    for (int f = 0; f < NF; f++){
        float c0=-INFINITY, c1=-INFINITY, c2=-INFINITY, c3=-INFINITY;
        #pragma unroll
        for (int hh = 0; hh < 2; hh++){
            int st = 2*f + hh;
            int cb = st & 3;
            mbar_wait(mb[cb], (st >> 2) & 1);

            const float4* bb = (const float4*)s->buf[cb];
            const unsigned* tbf = &s->tb[f*HH*WPR];

            #pragma unroll
            for (int k = 0; k < 3; k++){
                int r  = r0 + 16*k;         // row within half (0..47)
                int gr = hh*HROWS + r;      // global row (0..95)
                float4 x4 = bb[r*24 + fc];
                unsigned tw = tbf[gr*WPR + wi] >> shb;
                unsigned pw = s->pb[gr*WPR + wi] >> shb;
                float rmax = -INFINITY;
                float xs[4] = {x4.x, x4.y, x4.z, x4.w};
                #pragma unroll
                for (int j = 0; j < 4; j++){
                    float x = ((pw >> j) & 1u) ? 0.f : xs[j];
                    bool tt = (tw >> j) & 1u;
                    float th = tanh_approx(0.5f * x);
                    thsum += th;
                    if (tt) thp += th;
                    float sgn = tt ? 0.5f : -0.5f;
                    float pt  = fmaf(sgn, th, 0.5f);
                    float qv  = 1.f - pt;
                    float l   = __log2f(fmaxf(pt, 1e-12f));
                    float cf  = tt ? (-0.25f*LN2F) : (-0.75f*LN2F);
                    focal = fmaf(cf*l, qv*qv, focal);
                    rmax = fmaxf(rmax, x);
                    if      (j == 0) c0 = fmaxf(c0, x);
                    else if (j == 1) c1 = fmaxf(c1, x);
                    else if (j == 2) c2 = fmaxf(c2, x);
                    else             c3 = fmaxf(c3, x);
                }
                s->rowpart[gr*25 + fc] = rmax;
            }
            if (hh == 1)
                ((float4*)s->colpart)[r0*24 + fc] = make_float4(c0, c1, c2, c3);
            __syncthreads();   // buffer consumed, rowpart (and colpart) visible

            // refill this ring slot with step st+4
            if (tid == 0 && st + 4 < NSTEP){
                int st2 = st + 4;
                int f2 = st2 >> 1, h2 = st2 & 1;
                mbar_expect_tx(mb[cb], HBYTES);
                bulk_g2s(ba[cb], base0 + (size_t)f2*fstride + h2*HELEM, HBYTES, mb[cb]);
            }
        }

        // projection tail for this f (both halves of rowpart/colpart complete)
        int bf = b*NF + f;
        float a = 0.f, bs = 0.f;
        if (tid < 96){
            int h = tid; float m = -INFINITY;
            #pragma unroll
            for (int c = 0; c < 24; c++) m = fmaxf(m, s->rowpart[h*25 + c]);
            float sp = sigf(m);
            a = sp; bs = sp * __ldg(&g_tcm[bf*HH + h]);
        } else if (tid < 192){
            int w = tid - 96; float m = -INFINITY;
            #pragma unroll
            for (int g = 0; g < 16; g++) m = fmaxf(m, s->colpart[g*WW + w]);
            float sp = sigf(m);
            a = sp; bs = sp * __ldg(&g_trm[bf*WW + w]);
        }
        if (tid < 192){
            #pragma unroll
            for (int off = 16; off; off >>= 1){
                a  += __shfl_down_sync(0xffffffffu, a,  off);
                bs += __shfl_down_sync(0xffffffffu, bs, off);
            }
            if (lane == 0){ s->red2[wid][0] = a; s->red2[wid][1] = bs; }
        }
        __syncthreads();
        if (tid == 0){
            s->acc[0] += s->red2[0][0] + s->red2[1][0] + s->red2[2][0];  // SX
            s->acc[1] += s->red2[0][1] + s->red2[1][1] + s->red2[2][1];  // STX
            s->acc[2] += s->red2[3][0] + s->red2[4][0] + s->red2[5][0];  // SY
            s->acc[3] += s->red2[3][1] + s->red2[4][1] + s->red2[5][1];  // STY
        }
        __syncthreads();   // protect red2 / rowpart / colpart before next f
    }

    // block reduction of focal / thsum / thp (12 warps)
    #pragma unroll
    for (int off = 16; off; off >>= 1){
        focal += __shfl_down_sync(0xffffffffu, focal, off);
        thsum += __shfl_down_sync(0xffffffffu, thsum, off);
        thp   += __shfl_down_sync(0xffffffffu, thp,   off);
    }
    if (lane == 0){ s->red[wid*3] = focal; s->red[wid*3+1] = thsum; s->red[wid*3+2] = thp; }
    __syncthreads();

    // per-(b,q) scalar costs: warp 0, lanes 0..7 handle f=lane
    if (wid == 0){
        float TS=0, TTY=0, TTX=0, wsum=0, cc=0, bbsum=0, gsum=0;
        if (lane < NF){
            int f = lane, bf = b*NF + f;
            TS  = g_tscal[bf*4+0];
            TTY = g_tscal[bf*4+1];
            TTX = g_tscal[bf*4+2];

            float wf = (tvalid[bf] != 0) ? 1.f : 0.f;
            wsum = wf;
            float lg = logits[bf*NQ + q];
            float pp;
            if (lg >= 0.f){ float e = expf(-lg); pp = 1.f/(1.f+e); }
            else          { float e = expf( lg); pp = e/(1.f+e); }
            float pos = 0.25f*(1.f-pp)*(1.f-pp)*(-logf(pp + 1e-8f));
            float neg = 0.75f*pp*pp*(-logf(1.f - pp + 1e-8f));
            cc = (pos - neg)*wf;

            const float* sb = boxes + (size_t)(bf*NQ + q)*4;
            const float* tb = tbox  + (size_t)bf*4;
            float scx=sb[0], scy=sb[1], sw=sb[2], sh=sb[3];
            float tcx=tb[0], tcy=tb[1], tw=tb[2], th=tb[3];
            bbsum = fabsf(scx-tcx) + fabsf(scy-tcy) + fabsf(sw-tw) + fabsf(sh-th);

            float sx0=scx-0.5f*sw, sy0=scy-0.5f*sh, sx1=scx+0.5f*sw, sy1=scy+0.5f*sh;
            float tx0=tcx-0.5f*tw, ty0=tcy-0.5f*th, tx1=tcx+0.5f*tw, ty1=tcy+0.5f*th;
            float a1=(sx1-sx0)*(sy1-sy0);
            float a2=(tx1-tx0)*(ty1-ty0);
            float ltx=fmaxf(sx0,tx0), lty=fmaxf(sy0,ty0);
            float rbx=fminf(sx1,tx1), rby=fminf(sy1,ty1);
            float iw=fmaxf(rbx-ltx,0.f), ih=fmaxf(rby-lty,0.f);
            float inter=iw*ih;
            float uni=a1+a2-inter;
            float iou=inter/uni;
            float cx0=fminf(sx0,tx0), cy0=fminf(sy0,ty0);
            float cx1=fmaxf(sx1,tx1), cy1=fmaxf(sy1,ty1);
            float cw=fmaxf(cx1-cx0,0.f), ch=fmaxf(cy1-cy0,0.f);
            float ac=cw*ch;
            gsum = iou - (ac-uni)/ac;
        }
        #pragma unroll
        for (int off = 4; off; off >>= 1){
            TS    += __shfl_down_sync(0xffffffffu, TS,    off);
            TTY   += __shfl_down_sync(0xffffffffu, TTY,   off);
            TTX   += __shfl_down_sync(0xffffffffu, TTX,   off);
            wsum  += __shfl_down_sync(0xffffffffu, wsum,  off);
            cc    += __shfl_down_sync(0xffffffffu, cc,    off);
            bbsum += __shfl_down_sync(0xffffffffu, bbsum, off);
            gsum  += __shfl_down_sync(0xffffffffu, gsum,  off);
        }
        if (lane == 0){
            float F=0, TH=0, TP=0;
            #pragma unroll
            for (int w = 0; w < 12; w++){ F += s->red[w*3]; TH += s->red[w*3+1]; TP += s->red[w*3+2]; }
            float S  = 0.5f*(float)DTOT + 0.5f*TH;
            float ST = 0.5f*TS + 0.5f*TP;
            float cost_mask = F / (float)DTOT;
            float cost_dice = -(2.f*ST + 1.f) / (S + TS + 1.f);
            float cost_proj = -0.5f * ( (2.f*s->acc[1] + 1.f)/(s->acc[0] + TTX + 1.f)
                                      + (2.f*s->acc[3] + 1.f)/(s->acc[2] + TTY + 1.f) );
            outf[b*NQ + q] = cc/wsum + bbsum/(float)NF - gsum/(float)NF
                           + cost_mask + cost_dice + cost_proj;
            __threadfence();
            unsigned prev = atomicAdd(&g_count, 1u);
            s->isLast = (prev == (unsigned)(NBQ - 1));
        }
    }
    __syncthreads();
    if (!s->isLast) return;
    __threadfence();

    // ---------------- last-block argmin over outf[0..599] ----------------
    for (int b2 = 0; b2 < BS; b2++){
        float v = (tid < NQ) ? outf[b2*NQ + tid] : INFINITY;
        int idx = tid;
        #pragma unroll
        for (int off = 16; off; off >>= 1){
            float v2 = __shfl_down_sync(0xffffffffu, v, off);
            int   i2 = __shfl_down_sync(0xffffffffu, idx, off);
            if (v2 < v || (v2 == v && i2 < idx)){ v = v2; idx = i2; }
        }
        if (lane == 0){ s->avm[wid] = v; s->aim[wid] = idx; }
        __syncthreads();
        if (tid == 0){
            float bv = s->avm[0]; int bi = s->aim[0];
            #pragma unroll
            for (int w = 1; w < 12; w++){
                if (s->avm[w] < bv || (s->avm[w] == bv && s->aim[w] < bi)){ bv = s->avm[w]; bi = s->aim[w]; }
            }
            if (out_size == 608){
                long long* ip = (long long*)(outf + BS*NQ);
                ip[b2]      = (long long)bi;
                ip[BS + b2] = 0LL;
            } else if (out_size >= BS*NQ + 2*BS){
                outf[BS*NQ + b2]      = (float)bi;
                outf[BS*NQ + BS + b2] = 0.f;
            }
        }
        __syncthreads();
    }
    if (tid == 0) g_count = 0;   // reset for next graph replay
}

// ---------------- launch ----------------
extern "C" void kernel_launch(void* const* d_in, const int* in_sizes, int n_in,
                              void* d_out, int out_size)
{
    const float* logits = (const float*)d_in[0];
    const float* boxes  = (const float*)d_in[1];
    const float* masks  = (const float*)d_in[2];
    const float* tmask  = (const float*)d_in[3];
    const float* tbox   = (const float*)d_in[4];
    const int*   tvalid = (const int*)d_in[5];
    const unsigned char* pad = (const unsigned char*)d_in[6];
    float* outf = (float*)d_out;

    cudaFuncSetAttribute(main_kernel, cudaFuncAttributeMaxDynamicSharedMemorySize,
                         (int)sizeof(SmLayout));

    tgt_kernel <<<BS*NF, 256>>>(tmask, pad);
    main_kernel<<<NBQ,   THR, sizeof(SmLayout)>>>(masks, logits, boxes, tbox, tvalid, outf, out_size);
}